// round 2
// baseline (speedup 1.0000x reference)
#include <cuda_runtime.h>

#define NB      8
#define SEQ     1024
#define HIDDEN  1024
#define NHEADS  16
#define DHEAD   64
#define MTOT    (NB*SEQ)        // 8192
#define SZTERM  1.024e-5f       // S * ZERO = 1024 * 1e-8

// ---------------- scratch (no allocations allowed) ----------------
__device__ float g_q[NB*NHEADS*SEQ*DHEAD];     // [b][h][s][d]
__device__ float g_k[NB*NHEADS*SEQ*DHEAD];
__device__ float g_v[NB*NHEADS*SEQ*DHEAD];
__device__ float g_ctx[NB*SEQ*HIDDEN];         // [b][s][h*64+d]

// ---------------- generic GEMM: C = A[M,K] @ W[N,K]^T + bias ----------------
// M=8192, N=K=1024. head_layout=1 writes [b][h][s][d] scratch layout.
__global__ __launch_bounds__(256, 2)
void gemm_bias(const float* __restrict__ A, const float* __restrict__ W,
               const float* __restrict__ bias, float* __restrict__ C,
               int head_layout)
{
    __shared__ float As[8][132];
    __shared__ float Bs[8][132];

    const int tid = threadIdx.x;
    const int m0 = blockIdx.y * 128;
    const int n0 = blockIdx.x * 128;
    const int ty = tid >> 4;          // 0..15 -> 8 output rows each
    const int tx = tid & 15;          // 0..15 -> 8 output cols each
    const int lr = tid >> 1;          // 0..127 loader row
    const int lk = (tid & 1) << 2;    // 0 or 4 loader k-offset

    const float* Ap = A + (size_t)(m0 + lr) * HIDDEN + lk;
    const float* Wp = W + (size_t)(n0 + lr) * HIDDEN + lk;

    float acc[8][8];
#pragma unroll
    for (int i = 0; i < 8; i++)
#pragma unroll
        for (int j = 0; j < 8; j++) acc[i][j] = 0.0f;

    for (int k0 = 0; k0 < HIDDEN; k0 += 8) {
        float4 av = *(const float4*)(Ap + k0);
        float4 wv = *(const float4*)(Wp + k0);
        __syncthreads();
        As[lk+0][lr] = av.x; As[lk+1][lr] = av.y; As[lk+2][lr] = av.z; As[lk+3][lr] = av.w;
        Bs[lk+0][lr] = wv.x; Bs[lk+1][lr] = wv.y; Bs[lk+2][lr] = wv.z; Bs[lk+3][lr] = wv.w;
        __syncthreads();
#pragma unroll
        for (int kk = 0; kk < 8; kk++) {
            float a[8], b[8];
            *(float4*)&a[0] = *(const float4*)&As[kk][ty*8];
            *(float4*)&a[4] = *(const float4*)&As[kk][ty*8+4];
            *(float4*)&b[0] = *(const float4*)&Bs[kk][tx*8];
            *(float4*)&b[4] = *(const float4*)&Bs[kk][tx*8+4];
#pragma unroll
            for (int i = 0; i < 8; i++)
#pragma unroll
                for (int j = 0; j < 8; j++)
                    acc[i][j] += a[i] * b[j];
        }
    }

#pragma unroll
    for (int i = 0; i < 8; i++) {
        const int m = m0 + ty*8 + i;
        const int bb = m >> 10;           // batch
        const int ss = m & 1023;          // seq pos
#pragma unroll
        for (int j = 0; j < 8; j++) {
            const int n = n0 + tx*8 + j;
            const float v = acc[i][j] + bias[n];
            if (head_layout) {
                // [b][h][s][d]
                C[(((size_t)(bb*NHEADS + (n >> 6)))*SEQ + ss)*DHEAD + (n & 63)] = v;
            } else {
                C[(size_t)m * HIDDEN + n] = v;
            }
        }
    }
}

// ---------------- flash attention with exact mask renormalization ----------------
// per block: one (b,h), 64 query rows.  smem (dynamic):
//   Qs[64][68]  transposed [d][q]
//   Ks[64][68]  transposed [d][k]
//   Vs[64][68]  [k][d]
//   Ps[64][68]  [q][k]
//   Kms[64]
#define FPAD 68
#define FTILE (64*FPAD)
#define FLASH_SMEM ((4*FTILE + 64) * sizeof(float))

__global__ __launch_bounds__(256)
void flash_attn(const float* __restrict__ Qh, const float* __restrict__ Kh,
                const float* __restrict__ Vh, const float* __restrict__ Qmask,
                const float* __restrict__ Kmask, float* __restrict__ ctx)
{
    extern __shared__ float sm[];
    float* Qs  = sm;
    float* Ks  = sm + FTILE;
    float* Vs  = sm + 2*FTILE;
    float* Ps  = sm + 3*FTILE;
    float* Kms = sm + 4*FTILE;

    const int tid = threadIdx.x;
    const int q0  = blockIdx.x * 64;
    const int h   = blockIdx.y;
    const int b   = blockIdx.z;
    const int bh  = b*NHEADS + h;
    const int ty  = tid >> 4;   // 0..15 -> 4 q rows
    const int tx  = tid & 15;   // 0..15 -> 4 k cols / d cols

    const float* Qbase = Qh + ((size_t)bh*SEQ + q0) * DHEAD;

    // load Q tile transposed: Qs[d][q]
#pragma unroll
    for (int it = 0; it < 4; it++) {
        int f  = tid + it*256;       // 0..1023
        int r  = f >> 4;             // row 0..63
        int c4 = (f & 15) * 4;       // d 0,4,..,60
        float4 v = *(const float4*)(Qbase + (size_t)r*DHEAD + c4);
        Qs[(c4+0)*FPAD + r] = v.x;
        Qs[(c4+1)*FPAD + r] = v.y;
        Qs[(c4+2)*FPAD + r] = v.z;
        Qs[(c4+3)*FPAD + r] = v.w;
    }

    float m_[4], l_[4], lm_[4], o[4][4];
#pragma unroll
    for (int i = 0; i < 4; i++) {
        m_[i] = -1e30f; l_[i] = 0.0f; lm_[i] = 0.0f;
#pragma unroll
        for (int j = 0; j < 4; j++) o[i][j] = 0.0f;
    }

    for (int kt = 0; kt < SEQ; kt += 64) {
        __syncthreads();  // previous tile consumers done (also guards Q store on iter 0)

        const float* Kbase = Kh + ((size_t)bh*SEQ + kt) * DHEAD;
        const float* Vbase = Vh + ((size_t)bh*SEQ + kt) * DHEAD;
#pragma unroll
        for (int it = 0; it < 4; it++) {
            int f  = tid + it*256;
            int r  = f >> 4;
            int c4 = (f & 15) * 4;
            float4 kv = *(const float4*)(Kbase + (size_t)r*DHEAD + c4);
            Ks[(c4+0)*FPAD + r] = kv.x;
            Ks[(c4+1)*FPAD + r] = kv.y;
            Ks[(c4+2)*FPAD + r] = kv.z;
            Ks[(c4+3)*FPAD + r] = kv.w;
            float4 vv = *(const float4*)(Vbase + (size_t)r*DHEAD + c4);
            *(float4*)&Vs[r*FPAD + c4] = vv;
        }
        if (tid < 64) Kms[tid] = Kmask[(size_t)b*SEQ + kt + tid];
        __syncthreads();

        // S tile: s[i][j] = (q . k) * 8
        float s_[4][4];
#pragma unroll
        for (int i = 0; i < 4; i++)
#pragma unroll
            for (int j = 0; j < 4; j++) s_[i][j] = 0.0f;

        for (int d = 0; d < DHEAD; d++) {
            float4 qa = *(const float4*)&Qs[d*FPAD + ty*4];
            float4 kb = *(const float4*)&Ks[d*FPAD + tx*4];
            float aq[4] = {qa.x, qa.y, qa.z, qa.w};
            float bk[4] = {kb.x, kb.y, kb.z, kb.w};
#pragma unroll
            for (int i = 0; i < 4; i++)
#pragma unroll
                for (int j = 0; j < 4; j++)
                    s_[i][j] += aq[i] * bk[j];
        }

        float kmv[4];
#pragma unroll
        for (int j = 0; j < 4; j++) kmv[j] = Kms[tx*4 + j];

#pragma unroll
        for (int i = 0; i < 4; i++) {
            float rmax = -1e30f;
#pragma unroll
            for (int j = 0; j < 4; j++) {
                s_[i][j] *= 8.0f;                       // * sqrt(DH)
                rmax = fmaxf(rmax, s_[i][j]);
            }
#pragma unroll
            for (int off = 8; off > 0; off >>= 1)
                rmax = fmaxf(rmax, __shfl_xor_sync(0xffffffffu, rmax, off));

            float mnew = fmaxf(m_[i], rmax);
            float fac  = __expf(m_[i] - mnew);
            float suml = 0.0f, sumlm = 0.0f;
#pragma unroll
            for (int j = 0; j < 4; j++) {
                float e = __expf(s_[i][j] - mnew);
                float p = e * kmv[j];
                s_[i][j] = p;                           // masked prob for PV
                suml  += e;
                sumlm += p;
            }
#pragma unroll
            for (int off = 8; off > 0; off >>= 1) {
                suml  += __shfl_xor_sync(0xffffffffu, suml,  off);
                sumlm += __shfl_xor_sync(0xffffffffu, sumlm, off);
            }
            l_[i]  = l_[i]*fac + suml;
            lm_[i] = lm_[i]*fac + sumlm;
            m_[i]  = mnew;
#pragma unroll
            for (int j = 0; j < 4; j++) o[i][j] *= fac;

            *(float4*)&Ps[(ty*4 + i)*FPAD + tx*4] =
                make_float4(s_[i][0], s_[i][1], s_[i][2], s_[i][3]);
        }
        __syncthreads();

        // O += P @ V
        for (int k = 0; k < 64; k++) {
            float4 vv = *(const float4*)&Vs[k*FPAD + tx*4];
            float p0 = Ps[(ty*4+0)*FPAD + k];
            float p1 = Ps[(ty*4+1)*FPAD + k];
            float p2 = Ps[(ty*4+2)*FPAD + k];
            float p3 = Ps[(ty*4+3)*FPAD + k];
            o[0][0] += p0*vv.x; o[0][1] += p0*vv.y; o[0][2] += p0*vv.z; o[0][3] += p0*vv.w;
            o[1][0] += p1*vv.x; o[1][1] += p1*vv.y; o[1][2] += p1*vv.z; o[1][3] += p1*vv.w;
            o[2][0] += p2*vv.x; o[2][1] += p2*vv.y; o[2][2] += p2*vv.z; o[2][3] += p2*vv.w;
            o[3][0] += p3*vv.x; o[3][1] += p3*vv.y; o[3][2] += p3*vv.z; o[3][3] += p3*vv.w;
        }
    }

    // epilogue: out = Qm * o / (lm + l*S*ZERO), write ctx[b][q][h*64+d]
#pragma unroll
    for (int i = 0; i < 4; i++) {
        const int q = q0 + ty*4 + i;
        const float qm  = Qmask[(size_t)b*SEQ + q];
        const float inv = qm / (lm_[i] + l_[i]*SZTERM);
        float4 res = make_float4(o[i][0]*inv, o[i][1]*inv, o[i][2]*inv, o[i][3]*inv);
        *(float4*)&g_ctx[((size_t)b*SEQ + q)*HIDDEN + h*DHEAD + tx*4] = res;
    }
    (void)ctx;
}

// ---------------- launch ----------------
extern "C" void kernel_launch(void* const* d_in, const int* in_sizes, int n_in,
                              void* d_out, int out_size)
{
    const float* Q   = (const float*)d_in[0];
    const float* K   = (const float*)d_in[1];
    const float* V   = (const float*)d_in[2];
    const float* Qm  = (const float*)d_in[3];
    const float* Km  = (const float*)d_in[4];
    const float* Wq  = (const float*)d_in[5];
    const float* bq  = (const float*)d_in[6];
    const float* Wk  = (const float*)d_in[7];
    const float* bk  = (const float*)d_in[8];
    const float* Wv  = (const float*)d_in[9];
    const float* bv  = (const float*)d_in[10];
    const float* Wo  = (const float*)d_in[11];
    const float* bo  = (const float*)d_in[12];
    float* out = (float*)d_out;

    float *gq, *gk, *gv, *gctx;
    cudaGetSymbolAddress((void**)&gq,   g_q);
    cudaGetSymbolAddress((void**)&gk,   g_k);
    cudaGetSymbolAddress((void**)&gv,   g_v);
    cudaGetSymbolAddress((void**)&gctx, g_ctx);

    cudaFuncSetAttribute(flash_attn, cudaFuncAttributeMaxDynamicSharedMemorySize,
                         (int)FLASH_SMEM);

    dim3 gblk(256);
    dim3 ggrd(HIDDEN/128, MTOT/128);           // 8 x 64

    gemm_bias<<<ggrd, gblk>>>(Q, Wq, bq, gq, 1);
    gemm_bias<<<ggrd, gblk>>>(K, Wk, bk, gk, 1);
    gemm_bias<<<ggrd, gblk>>>(V, Wv, bv, gv, 1);

    dim3 fgrd(SEQ/64, NHEADS, NB);             // 16 x 16 x 8
    flash_attn<<<fgrd, 256, FLASH_SMEM>>>(gq, gk, gv, Qm, Km, gctx);

    gemm_bias<<<ggrd, gblk>>>(gctx, Wo, bo, out, 0);

    (void)in_sizes; (void)n_in; (void)out_size;
}